// round 15
// baseline (speedup 1.0000x reference)
#include <cuda_runtime.h>
#include <cuda_fp16.h>
#include <math.h>

// Problem constants (fixed by reference setup_inputs):
//   n = 100000 nodes, seq_len = 4, hidden = 128, n_edges = 1.6M
#define MAX_N      100000
#define MAX_EDGES  1600000
#define HIDDEN     128
#define SEQ_STRIDE (4 * 128)   // floats per node in semantics

// Scratch (device globals; no allocations allowed).
__device__ float  g_mean[MAX_N * HIDDEN];   // aggregated means (fp32)
__device__ __half g_sem16[MAX_N * HIDDEN];  // fp16 copy of sem[:,0,:]
__device__ int    g_cnt[MAX_N];             // per-target in-degree
__device__ int    g_off[MAX_N + 1];         // CSR-by-target offsets
__device__ int    g_cursor[MAX_N];          // placement cursors
__device__ int    g_srcs[MAX_EDGES];        // source ids sorted by target
__device__ int    g_idx_is_64;              // 1 = int64 edge_index, 0 = int32

// ---------------------------------------------------------------------------
// f32x2 helpers (fma.rn.f32x2 — 2 FMA per issue slot).
// ---------------------------------------------------------------------------
__device__ __forceinline__ unsigned long long pack_f32x2(float lo, float hi) {
    unsigned long long r;
    asm("mov.b64 %0, {%1, %2};" : "=l"(r) : "f"(lo), "f"(hi));
    return r;
}
__device__ __forceinline__ void fma_f32x2(unsigned long long& d,
                                          unsigned long long a,
                                          unsigned long long b) {
    asm("fma.rn.f32x2 %0, %1, %2, %0;" : "+l"(d) : "l"(a), "l"(b));
}
__device__ __forceinline__ float hsum_f32x2(unsigned long long v) {
    float lo, hi;
    asm("mov.b64 {%0, %1}, %2;" : "=f"(lo), "=f"(hi) : "l"(v));
    return lo + hi;
}

// ---------------------------------------------------------------------------
// Kernel 0: zero g_cnt + convert sem[:,0,:] -> fp16 + dtype probe.
// ---------------------------------------------------------------------------
__global__ void prep_kernel(const float* __restrict__ sem,
                            const long long* __restrict__ ei64,
                            long long n, int n_nodes) {
    int tid = blockIdx.x * blockDim.x + threadIdx.x;
    int nt  = gridDim.x * blockDim.x;

    for (int i = tid; i < n_nodes; i += nt) g_cnt[i] = 0;

    const int n_oct = n_nodes * (HIDDEN / 8);
    for (int i = tid; i < n_oct; i += nt) {
        int node = i >> 4;           // 16 octs of 8 floats per node
        int oct  = i & 15;
        const float4* src = (const float4*)(sem + (size_t)node * SEQ_STRIDE + oct * 8);
        float4 a = __ldg(src);
        float4 b = __ldg(src + 1);
        __half2 h[4];
        h[0] = __floats2half2_rn(a.x, a.y);
        h[1] = __floats2half2_rn(a.z, a.w);
        h[2] = __floats2half2_rn(b.x, b.y);
        h[3] = __floats2half2_rn(b.z, b.w);
        *(uint4*)(g_sem16 + (size_t)node * HIDDEN + oct * 8) = *(uint4*)h;
    }

    if (blockIdx.x == 0 && threadIdx.x < 32) {
        int lane = threadIdx.x;
        int bad = 0;
        #pragma unroll
        for (int i = 0; i < 8; i++) {
            long long v = ei64[lane * 8 + i];
            if (v < 0 || v >= n) bad = 1;
        }
        unsigned m = __ballot_sync(0xFFFFFFFFu, bad);
        if (lane == 0) g_idx_is_64 = (m == 0u) ? 1 : 0;
    }
}

// ---------------------------------------------------------------------------
// Kernel 1: histogram of TARGET in-degree.
// ---------------------------------------------------------------------------
__global__ void hist_kernel(const void* __restrict__ ei_raw, int n_edges) {
    int e = blockIdx.x * blockDim.x + threadIdx.x;
    if (e >= n_edges) return;
    int tgt;
    if (g_idx_is_64) {
        longlong2 p = __ldg((const longlong2*)ei_raw + e);
        tgt = (int)p.y;
    } else {
        int2 p = __ldg((const int2*)ei_raw + e);
        tgt = p.y;
    }
    atomicAdd(&g_cnt[tgt], 1);
}

// ---------------------------------------------------------------------------
// Kernel 2: single-block exclusive scan over counts -> g_off, g_cursor.
// ---------------------------------------------------------------------------
#define SCAN_THREADS 1024
__global__ void scan_kernel(int n) {
    __shared__ int ssum[SCAN_THREADS];
    int t = threadIdx.x;
    int chunk = (n + SCAN_THREADS - 1) / SCAN_THREADS;
    int lo = t * chunk;
    int hi = min(lo + chunk, n);

    int sum = 0;
    for (int i = lo; i < hi; i++) sum += g_cnt[i];
    ssum[t] = sum;
    __syncthreads();

    for (int off = 1; off < SCAN_THREADS; off <<= 1) {
        int v = (t >= off) ? ssum[t - off] : 0;
        __syncthreads();
        ssum[t] += v;
        __syncthreads();
    }

    int run = (t == 0) ? 0 : ssum[t - 1];
    for (int i = lo; i < hi; i++) {
        int c = g_cnt[i];
        g_off[i] = run;
        g_cursor[i] = run;
        run += c;
    }
    if (t == SCAN_THREADS - 1) g_off[n] = run;
}

// ---------------------------------------------------------------------------
// Kernel 3: placement — bucket SOURCE ids by TARGET (counting sort on tgt).
// ---------------------------------------------------------------------------
__global__ void place_kernel(const void* __restrict__ ei_raw, int n_edges) {
    int e = blockIdx.x * blockDim.x + threadIdx.x;
    if (e >= n_edges) return;
    int src, tgt;
    if (g_idx_is_64) {
        longlong2 p = __ldg((const longlong2*)ei_raw + e);
        src = (int)p.x; tgt = (int)p.y;
    } else {
        int2 p = __ldg((const int2*)ei_raw + e);
        src = p.x; tgt = p.y;
    }
    int pos = atomicAdd(&g_cursor[tgt], 1);
    g_srcs[pos] = src;
}

// ---------------------------------------------------------------------------
// Kernel 4: CSR gather-mean. Warp per node; fully-predicated 8-edge batches
// so EVERY batch (including tails) runs at MLP=8 on the idx->row chain.
// No atomics, no RMW: 410 MB of L2-resident reads + 51 MB coalesced writes
// (vs ~2 GB incl. RED RMW for the scatter).
// ---------------------------------------------------------------------------
__global__ void gather_mean_kernel(int n) {
    const int warp = (blockIdx.x * blockDim.x + threadIdx.x) >> 5;
    const int lane = threadIdx.x & 31;
    if (warp >= n) return;

    const int beg = g_off[warp];
    const int end = g_off[warp + 1];

    float4 acc = make_float4(0.f, 0.f, 0.f, 0.f);

    for (int e = beg; e < end; e += 8) {
        int idx[8];
        #pragma unroll
        for (int u = 0; u < 8; u++)
            idx[u] = __ldg(g_srcs + ((e + u < end) ? e + u : beg));
        uint2 v[8];
        #pragma unroll
        for (int u = 0; u < 8; u++)
            v[u] = __ldg((const uint2*)(g_sem16 + (size_t)idx[u] * HIDDEN) + lane);
        #pragma unroll
        for (int u = 0; u < 8; u++) {
            if (e + u < end) {
                float2 f0 = __half22float2(*(__half2*)&v[u].x);
                float2 f1 = __half22float2(*(__half2*)&v[u].y);
                acc.x += f0.x; acc.y += f0.y;
                acc.z += f1.x; acc.w += f1.y;
            }
        }
    }

    const float inv = 1.0f / (float)max(end - beg, 1);
    *(float4*)(g_mean + (size_t)warp * HIDDEN + lane * 4) =
        make_float4(acc.x * inv, acc.y * inv, acc.z * inv, acc.w * inv);
}

// ---------------------------------------------------------------------------
// Kernel 5: (means @ W) -> exact GELU -> out. (R14 GEMM, divisor removed.)
// ---------------------------------------------------------------------------
#define RPB 16
__global__ void gemm_gelu_kernel(const float* __restrict__ W,
                                 float* __restrict__ out,
                                 int n) {
    __shared__ float4 s4[RPB][HIDDEN / 4];
    const int r0 = blockIdx.x * RPB;
    const int j  = threadIdx.x;   // 0..127 output column

    const float4 z = make_float4(0.f, 0.f, 0.f, 0.f);
    for (int i = threadIdx.x; i < RPB * (HIDDEN / 4); i += HIDDEN) {
        int r  = i >> 5;
        int kq = i & 31;
        int row = r0 + r;
        s4[r][kq] = (row < n)
            ? ((const float4*)(g_mean + (size_t)row * HIDDEN))[kq] : z;
    }
    __syncthreads();

    unsigned long long acc2[RPB];
    #pragma unroll
    for (int r = 0; r < RPB; r++) acc2[r] = 0ull;

    #pragma unroll 4
    for (int kq = 0; kq < HIDDEN / 4; kq++) {
        const float w0 = __ldg(W + (4 * kq + 0) * HIDDEN + j);
        const float w1 = __ldg(W + (4 * kq + 1) * HIDDEN + j);
        const float w2 = __ldg(W + (4 * kq + 2) * HIDDEN + j);
        const float w3 = __ldg(W + (4 * kq + 3) * HIDDEN + j);
        const unsigned long long w01 = pack_f32x2(w0, w1);
        const unsigned long long w23 = pack_f32x2(w2, w3);
        #pragma unroll
        for (int r = 0; r < RPB; r++) {
            float4 sv = s4[r][kq];        // broadcast LDS.128
            const unsigned long long* sp = (const unsigned long long*)&sv;
            fma_f32x2(acc2[r], sp[0], w01);
            fma_f32x2(acc2[r], sp[1], w23);
        }
    }

    #pragma unroll
    for (int r = 0; r < RPB; r++) {
        int row = r0 + r;
        if (row < n) {
            float m = hsum_f32x2(acc2[r]);
            // exact GELU: 0.5*x*(1 + erf(x/sqrt(2)))
            out[(size_t)row * HIDDEN + j] =
                0.5f * m * (1.0f + erff(m * 0.70710678118654752f));
        }
    }
}

// ---------------------------------------------------------------------------
// kernel_launch: prep -> hist -> scan -> place -> gather -> gemm.
// All graph-capturable; no allocations; no RED/atomic in the hot path.
// Input order (metadata): semantics, attention_masks (unused), W, edge_index.
// ---------------------------------------------------------------------------
extern "C" void kernel_launch(void* const* d_in, const int* in_sizes, int n_in,
                              void* d_out, int out_size) {
    const float* sem = (const float*)d_in[0];
    const float* W   = (const float*)d_in[2];
    const void*  ei  = d_in[3];
    float* out = (float*)d_out;

    const int n       = in_sizes[0] / SEQ_STRIDE;   // 100000
    const int n_edges = in_sizes[3] / 2;            // 1600000

    prep_kernel<<<400, 512>>>(sem, (const long long*)ei, (long long)n, n);

    int eb = (n_edges + 511) / 512;
    hist_kernel<<<eb, 512>>>(ei, n_edges);
    scan_kernel<<<1, SCAN_THREADS>>>(n);
    place_kernel<<<eb, 512>>>(ei, n_edges);

    // warp per node, 8 warps per 256-thread block
    gather_mean_kernel<<<(n + 7) / 8, 256>>>(n);

    int gb = (n + RPB - 1) / RPB;
    gemm_gelu_kernel<<<gb, HIDDEN>>>(W, out, n);
}

// round 16
// speedup vs baseline: 1.3044x; 1.3044x over previous
#include <cuda_runtime.h>
#include <cuda_fp16.h>
#include <math.h>

// Problem constants (fixed by reference setup_inputs):
//   n = 100000 nodes, seq_len = 4, hidden = 128, n_edges = 1.6M
#define MAX_N      100000
#define HIDDEN     128
#define SEQ_STRIDE (4 * 128)   // floats per node in semantics

// Scratch (device globals; no allocations allowed).
__device__ float  g_sums[MAX_N * HIDDEN];   // 51.2 MB fp32 accumulators
__device__ float  g_cntf[MAX_N];            // per-target in-degree (float)
__device__ __half g_sem16[MAX_N * HIDDEN];  // fp16 copy of sem[:,0,:]
__device__ int    g_idx_is_64;              // 1 = int64 edge_index, 0 = int32

// ---------------------------------------------------------------------------
// f32x2 helpers (fma.rn.f32x2 — 2 FMA per issue slot).
// ---------------------------------------------------------------------------
__device__ __forceinline__ unsigned long long pack_f32x2(float lo, float hi) {
    unsigned long long r;
    asm("mov.b64 %0, {%1, %2};" : "=l"(r) : "f"(lo), "f"(hi));
    return r;
}
__device__ __forceinline__ void fma_f32x2(unsigned long long& d,
                                          unsigned long long a,
                                          unsigned long long b) {
    asm("fma.rn.f32x2 %0, %1, %2, %0;" : "+l"(d) : "l"(a), "l"(b));
}
__device__ __forceinline__ float hsum_f32x2(unsigned long long v) {
    float lo, hi;
    asm("mov.b64 {%0, %1}, %2;" : "=f"(lo), "=f"(hi) : "l"(v));
    return lo + hi;
}

// ---------------------------------------------------------------------------
// Kernel 0: zero g_sums/g_cntf (grid-stride) + dtype probe (block 0, warp 0).
// ---------------------------------------------------------------------------
__global__ void prep_kernel(const long long* __restrict__ ei64,
                            long long n, int n_nodes) {
    int tid = blockIdx.x * blockDim.x + threadIdx.x;
    int nt  = gridDim.x * blockDim.x;

    float4 z = make_float4(0.f, 0.f, 0.f, 0.f);
    float4* sums4 = (float4*)g_sums;
    const int n4 = n_nodes * (HIDDEN / 4);
    for (int i = tid; i < n4; i += nt) sums4[i] = z;
    for (int i = tid; i < n_nodes; i += nt) g_cntf[i] = 0.f;

    if (blockIdx.x == 0 && threadIdx.x < 32) {
        int lane = threadIdx.x;
        int bad = 0;
        #pragma unroll
        for (int i = 0; i < 8; i++) {
            long long v = ei64[lane * 8 + i];
            if (v < 0 || v >= n) bad = 1;
        }
        unsigned m = __ballot_sync(0xFFFFFFFFu, bad);
        if (lane == 0) g_idx_is_64 = (m == 0u) ? 1 : 0;
    }
}

// ---------------------------------------------------------------------------
// Kernel 1: convert sem[:,0,:] fp32 -> fp16 (halves the random gather bytes).
// ---------------------------------------------------------------------------
__global__ void cvt_kernel(const float* __restrict__ sem, int n_nodes) {
    int tid = blockIdx.x * blockDim.x + threadIdx.x;
    int nt  = gridDim.x * blockDim.x;
    const int n_oct = n_nodes * (HIDDEN / 8);
    for (int i = tid; i < n_oct; i += nt) {
        int node = i >> 4;           // 16 octs of 8 floats per node
        int oct  = i & 15;
        const float4* src = (const float4*)(sem + (size_t)node * SEQ_STRIDE + oct * 8);
        float4 a = __ldg(src);
        float4 b = __ldg(src + 1);
        __half2 h[4];
        h[0] = __floats2half2_rn(a.x, a.y);
        h[1] = __floats2half2_rn(a.z, a.w);
        h[2] = __floats2half2_rn(b.x, b.y);
        h[3] = __floats2half2_rn(b.z, b.w);
        *(uint4*)(g_sem16 + (size_t)node * HIDDEN + oct * 8) = *(uint4*)h;
    }
}

// ---------------------------------------------------------------------------
// Kernel 2: scatter, 4 independent edges per warp (the R13/R14 champion:
// MLP=4 on the idx->row chain, regs 30, occ 87%). Single launch.
// ---------------------------------------------------------------------------
#define EPW 4   // edges per warp
__global__ void __launch_bounds__(256)
scatter_kernel(const void* __restrict__ ei_raw, int n_edges) {
    const int warp = (blockIdx.x * blockDim.x + threadIdx.x) >> 5;
    const int lane = threadIdx.x & 31;
    const int e0 = warp * EPW;
    if (e0 >= n_edges) return;

    const int m = min(EPW, n_edges - e0);

    int srcs[EPW], tgts[EPW];
    if (g_idx_is_64) {
        const longlong2* ei = (const longlong2*)ei_raw;
        #pragma unroll
        for (int u = 0; u < EPW; u++) {
            longlong2 p = __ldg(ei + e0 + (u < m ? u : 0));
            srcs[u] = (int)p.x; tgts[u] = (int)p.y;
        }
    } else {
        const int2* ei = (const int2*)ei_raw;
        #pragma unroll
        for (int u = 0; u < EPW; u++) {
            int2 p = __ldg(ei + e0 + (u < m ? u : 0));
            srcs[u] = p.x; tgts[u] = p.y;
        }
    }

    // 4 independent 256 B row loads (8 B/lane each).
    uint2 v[EPW];
    #pragma unroll
    for (int u = 0; u < EPW; u++)
        v[u] = __ldg((const uint2*)(g_sem16 + (size_t)srcs[u] * HIDDEN) + lane);

    #pragma unroll
    for (int u = 0; u < EPW; u++) {
        if (u < m) {
            float2 f0 = __half22float2(*(__half2*)&v[u].x);
            float2 f1 = __half22float2(*(__half2*)&v[u].y);
            float* dst = g_sums + (size_t)tgts[u] * HIDDEN + lane * 4;
            asm volatile("red.global.add.v4.f32 [%0], {%1, %2, %3, %4};"
                         :: "l"(dst), "f"(f0.x), "f"(f0.y), "f"(f1.x), "f"(f1.y)
                         : "memory");
        }
    }

    if (lane < m) atomicAdd(&g_cntf[tgts[lane]], 1.0f);
}

// ---------------------------------------------------------------------------
// Kernel 3: fused (sums @ W) / max(cnt,1) -> exact GELU -> out.
// NEW mapping: TPB=128, thread owns 4 rows x 4 cols. Per kq (4 k-steps):
//   4x LDG.128 (W, coalesced) + 4x broadcast LDS.128 (s) + 32 FFMA2.
// LDS per FFMA2: 0.125 (was 0.5 -> measured ~100 us of MIO issue).
// ---------------------------------------------------------------------------
#define RPB 16
__global__ void __launch_bounds__(128)
gemm_mean_gelu_kernel(const float* __restrict__ W,
                      float* __restrict__ out,
                      int n) {
    __shared__ float4 s4[RPB][HIDDEN / 4];
    const int r0 = blockIdx.x * RPB;
    const int t  = threadIdx.x;

    const float4 z = make_float4(0.f, 0.f, 0.f, 0.f);
    for (int i = t; i < RPB * (HIDDEN / 4); i += 128) {
        int r  = i >> 5;
        int kq = i & 31;
        int row = r0 + r;
        s4[r][kq] = (row < n)
            ? ((const float4*)(g_sums + (size_t)row * HIDDEN))[kq] : z;
    }
    __syncthreads();

    const int rg = t >> 5;          // row group 0..3 (rows rg*4 .. rg*4+3)
    const int c  = (t & 31) * 4;    // column base

    unsigned long long acc2[4][4];  // [row][col], k-pair packed
    #pragma unroll
    for (int rr = 0; rr < 4; rr++)
        #pragma unroll
        for (int cc = 0; cc < 4; cc++) acc2[rr][cc] = 0ull;

    #pragma unroll 2
    for (int kq = 0; kq < HIDDEN / 4; kq++) {
        // W rows 4kq..4kq+3, columns c..c+3 (4 coalesced LDG.128)
        float4 wv0 = __ldg((const float4*)(W + (4 * kq + 0) * HIDDEN + c));
        float4 wv1 = __ldg((const float4*)(W + (4 * kq + 1) * HIDDEN + c));
        float4 wv2 = __ldg((const float4*)(W + (4 * kq + 2) * HIDDEN + c));
        float4 wv3 = __ldg((const float4*)(W + (4 * kq + 3) * HIDDEN + c));
        const float* w0 = (const float*)&wv0;
        const float* w1 = (const float*)&wv1;
        const float* w2 = (const float*)&wv2;
        const float* w3 = (const float*)&wv3;
        unsigned long long w01[4], w23[4];
        #pragma unroll
        for (int cc = 0; cc < 4; cc++) {
            w01[cc] = pack_f32x2(w0[cc], w1[cc]);
            w23[cc] = pack_f32x2(w2[cc], w3[cc]);
        }

        #pragma unroll
        for (int rr = 0; rr < 4; rr++) {
            float4 sv = s4[rg * 4 + rr][kq];   // broadcast LDS.128
            unsigned long long s01 = pack_f32x2(sv.x, sv.y);
            unsigned long long s23 = pack_f32x2(sv.z, sv.w);
            #pragma unroll
            for (int cc = 0; cc < 4; cc++) {
                fma_f32x2(acc2[rr][cc], s01, w01[cc]);
                fma_f32x2(acc2[rr][cc], s23, w23[cc]);
            }
        }
    }

    #pragma unroll
    for (int rr = 0; rr < 4; rr++) {
        int row = r0 + rg * 4 + rr;
        if (row < n) {
            float inv = 1.0f / fmaxf(g_cntf[row], 1.0f);
            float4 o;
            o.x = hsum_f32x2(acc2[rr][0]) * inv;
            o.y = hsum_f32x2(acc2[rr][1]) * inv;
            o.z = hsum_f32x2(acc2[rr][2]) * inv;
            o.w = hsum_f32x2(acc2[rr][3]) * inv;
            // exact GELU: 0.5*x*(1 + erf(x/sqrt(2)))
            o.x = 0.5f * o.x * (1.0f + erff(o.x * 0.70710678118654752f));
            o.y = 0.5f * o.y * (1.0f + erff(o.y * 0.70710678118654752f));
            o.z = 0.5f * o.z * (1.0f + erff(o.z * 0.70710678118654752f));
            o.w = 0.5f * o.w * (1.0f + erff(o.w * 0.70710678118654752f));
            *(float4*)(out + (size_t)row * HIDDEN + c) = o;
        }
    }
}

// ---------------------------------------------------------------------------
// kernel_launch: prep -> cvt -> scatter -> gemm. The gemm now sits at launch
// index 3 (ncu's observed capture slot) so next round gets its profile.
// All graph-capturable; no allocations.
// Input order (metadata): semantics, attention_masks (unused), W, edge_index.
// ---------------------------------------------------------------------------
extern "C" void kernel_launch(void* const* d_in, const int* in_sizes, int n_in,
                              void* d_out, int out_size) {
    const float* sem = (const float*)d_in[0];
    const float* W   = (const float*)d_in[2];
    const void*  ei  = d_in[3];
    float* out = (float*)d_out;

    const int n       = in_sizes[0] / SEQ_STRIDE;   // 100000
    const int n_edges = in_sizes[3] / 2;            // 1600000

    prep_kernel<<<400, 512>>>((const long long*)ei, (long long)n, n);
    cvt_kernel<<<400, 512>>>(sem, n);

    const int epb = 8 * EPW;    // 8 warps/block
    scatter_kernel<<<(n_edges + epb - 1) / epb, 256>>>(ei, n_edges);

    int gb = (n + RPB - 1) / RPB;
    gemm_mean_gelu_kernel<<<gb, 128>>>(W, out, n);
}